// round 1
// baseline (speedup 1.0000x reference)
#include <cuda_runtime.h>

// Problem constants
#define FE_   1024
#define T_    2048
#define B_    4
#define NCH_  128              // chunks over T for the x-sum
#define TPC_  (T_ / NCH_)      // 16 timesteps per chunk
#define EPS_  1e-5f

// Scratch (device globals — no allocation allowed)
__device__ float g_cc[2][FE_];             // [0]=cc_v, [1]=cc_o
__device__ float g_part[B_ * NCH_ * FE_];  // partial sums of x over T
__device__ float g_m1[B_ * FE_];           // (Σ_t x) ⊙ cc_v
__device__ float g_m2[B_ * FE_];           // (sv + T·v_bl) ⊙ cc_o
__device__ float g_z[B_ * FE_];            // final per-batch row

// ---------------------------------------------------------------------------
// Kernel 1: cond vectors. cc = LN(Wc @ c_flat) * g + b   for v (block 0) and
// o (block 1). Wc: [FE, 256] row-major, c_flat: [256].
// ---------------------------------------------------------------------------
__global__ void cond_kernel(const float* __restrict__ c,
                            const float* __restrict__ Wc_v,
                            const float* __restrict__ g_v,
                            const float* __restrict__ b_v,
                            const float* __restrict__ Wc_o,
                            const float* __restrict__ g_o,
                            const float* __restrict__ b_o)
{
    const float* Wc = (blockIdx.x == 0) ? Wc_v : Wc_o;
    const float* gg = (blockIdx.x == 0) ? g_v  : g_o;
    const float* bb = (blockIdx.x == 0) ? b_v  : b_o;
    float* outp = g_cc[blockIdx.x];

    __shared__ float s_c[256];
    __shared__ float s_cc[FE_];
    __shared__ float s_red[256];

    const int tid  = threadIdx.x;        // 0..255
    const int lane = tid & 31;
    const int warp = tid >> 5;           // 0..7

    s_c[tid] = c[tid];
    __syncthreads();

    // one warp per row, lanes stride the 256-wide dot product (coalesced)
    for (int r = warp; r < FE_; r += 8) {
        float acc = 0.f;
        #pragma unroll
        for (int k = 0; k < 8; k++) {
            int j = lane + k * 32;
            acc += Wc[r * 256 + j] * s_c[j];
        }
        #pragma unroll
        for (int off = 16; off; off >>= 1)
            acc += __shfl_down_sync(0xffffffffu, acc, off);
        if (lane == 0) s_cc[r] = acc;
    }
    __syncthreads();

    // mean over FE
    float v = s_cc[tid] + s_cc[tid + 256] + s_cc[tid + 512] + s_cc[tid + 768];
    s_red[tid] = v;
    __syncthreads();
    for (int off = 128; off; off >>= 1) {
        if (tid < off) s_red[tid] += s_red[tid + off];
        __syncthreads();
    }
    const float mu = s_red[0] * (1.0f / FE_);
    __syncthreads();

    // variance
    float d0 = s_cc[tid]       - mu, d1 = s_cc[tid + 256] - mu;
    float d2 = s_cc[tid + 512] - mu, d3 = s_cc[tid + 768] - mu;
    s_red[tid] = d0 * d0 + d1 * d1 + d2 * d2 + d3 * d3;
    __syncthreads();
    for (int off = 128; off; off >>= 1) {
        if (tid < off) s_red[tid] += s_red[tid + off];
        __syncthreads();
    }
    const float rstd = rsqrtf(s_red[0] * (1.0f / FE_) + EPS_);

    for (int i = tid; i < FE_; i += 256)
        outp[i] = (s_cc[i] - mu) * rstd * gg[i] + bb[i];
}

// ---------------------------------------------------------------------------
// Kernel 2: partial sums of x over T. x: [B, T, FE] f32 → float4 lanes.
// grid = B*NCH blocks of 256 threads; each block sums TPC timesteps.
// ---------------------------------------------------------------------------
__global__ void sumx_kernel(const float4* __restrict__ x)
{
    const int bc = blockIdx.x;            // 0..B*NCH-1
    const int b  = bc / NCH_;
    const int ch = bc % NCH_;
    const int j  = threadIdx.x;           // 0..255 (float4 lane)

    const float4* p = x + (size_t)b * (T_ * 256) + (size_t)ch * (TPC_ * 256) + j;
    float4 a = make_float4(0.f, 0.f, 0.f, 0.f);
    #pragma unroll
    for (int t = 0; t < TPC_; t++) {
        float4 u = p[(size_t)t * 256];
        a.x += u.x; a.y += u.y; a.z += u.z; a.w += u.w;
    }
    reinterpret_cast<float4*>(g_part)[(size_t)bc * 256 + j] = a;
}

// ---------------------------------------------------------------------------
// Kernel 3: reduce partials deterministically and modulate by cc_v.
// grid = B blocks of FE threads.
// ---------------------------------------------------------------------------
__global__ void reduce_mod_kernel()
{
    const int b = blockIdx.x;
    const int j = threadIdx.x;            // 0..1023
    float s = 0.f;
    #pragma unroll 8
    for (int ch = 0; ch < NCH_; ch++)
        s += g_part[((size_t)b * NCH_ + ch) * FE_ + j];
    g_m1[b * FE_ + j] = s * g_cc[0][j];
}

// ---------------------------------------------------------------------------
// Kernel 4 (used twice): out[b][row] = (Σ_j m[b][j]·W[row][j] + bias_scale·bias[row]) · post
// stage 0: m = g_m1, post = cc_o, out = g_m2   (v_Wl, bias=v_bl, scale=T)
// stage 1: m = g_m2, post = 1,    out = g_z    (o_Wl, bias=o_bl, scale=1)
// One block per row; the 4 batch dots share the W-row read.
// ---------------------------------------------------------------------------
__global__ void matvec_kernel(const float* __restrict__ W,
                              const float* __restrict__ bias,
                              float bias_scale, int stage)
{
    __shared__ float sm[4][FE_];
    __shared__ float sred[8][4];

    const int tid  = threadIdx.x;         // 0..255
    const int lane = tid & 31;
    const int warp = tid >> 5;
    const float* m = (stage == 0) ? g_m1 : g_m2;

    for (int i = tid; i < 4 * FE_; i += 256)
        (&sm[0][0])[i] = m[i];
    __syncthreads();

    const int row = blockIdx.x;
    const float* wr = W + (size_t)row * FE_;
    float a0 = 0.f, a1 = 0.f, a2 = 0.f, a3 = 0.f;
    #pragma unroll
    for (int k = 0; k < 4; k++) {
        int j = tid + k * 256;
        float w = wr[j];
        a0 += w * sm[0][j];
        a1 += w * sm[1][j];
        a2 += w * sm[2][j];
        a3 += w * sm[3][j];
    }
    #pragma unroll
    for (int off = 16; off; off >>= 1) {
        a0 += __shfl_down_sync(0xffffffffu, a0, off);
        a1 += __shfl_down_sync(0xffffffffu, a1, off);
        a2 += __shfl_down_sync(0xffffffffu, a2, off);
        a3 += __shfl_down_sync(0xffffffffu, a3, off);
    }
    if (lane == 0) {
        sred[warp][0] = a0; sred[warp][1] = a1;
        sred[warp][2] = a2; sred[warp][3] = a3;
    }
    __syncthreads();
    if (tid < 4) {
        float s = 0.f;
        #pragma unroll
        for (int w = 0; w < 8; w++) s += sred[w][tid];
        float val = s + bias_scale * bias[row];
        if (stage == 0) {
            val *= g_cc[1][row];
            g_m2[tid * FE_ + row] = val;
        } else {
            g_z[tid * FE_ + row] = val;
        }
    }
}

// ---------------------------------------------------------------------------
// Kernel 5: broadcast z[b] across all T timesteps of the output.
// out flat: [B, T, FE] → 2M float4 stores.
// ---------------------------------------------------------------------------
__global__ void bcast_kernel(float4* __restrict__ out)
{
    const int idx = blockIdx.x * blockDim.x + threadIdx.x;  // 0..2M-1
    const int b   = idx >> 19;        // T*256 float4 per batch = 524288
    const int j   = idx & 255;
    out[idx] = reinterpret_cast<const float4*>(g_z)[b * 256 + j];
}

// ---------------------------------------------------------------------------
extern "C" void kernel_launch(void* const* d_in, const int* in_sizes, int n_in,
                              void* d_out, int out_size)
{
    const float* x   = (const float*)d_in[0];
    const float* c   = (const float*)d_in[1];
    // q (3-7) and k (8-12) branches and C (2) cancel out analytically.
    const float* vWl = (const float*)d_in[13];
    const float* vbl = (const float*)d_in[14];
    const float* vWc = (const float*)d_in[15];
    const float* vg  = (const float*)d_in[16];
    const float* vb  = (const float*)d_in[17];
    const float* oWl = (const float*)d_in[18];
    const float* obl = (const float*)d_in[19];
    const float* oWc = (const float*)d_in[20];
    const float* og  = (const float*)d_in[21];
    const float* ob  = (const float*)d_in[22];

    cond_kernel<<<2, 256>>>(c, vWc, vg, vb, oWc, og, ob);
    sumx_kernel<<<B_ * NCH_, 256>>>((const float4*)x);
    reduce_mod_kernel<<<B_, FE_>>>();
    matvec_kernel<<<FE_, 256>>>(vWl, vbl, (float)T_, 0);
    matvec_kernel<<<FE_, 256>>>(oWl, obl, 1.0f, 1);
    bcast_kernel<<<(B_ * T_ * 256) / 256, 256>>>((float4*)d_out);
}

// round 2
// speedup vs baseline: 4.7141x; 4.7141x over previous
#include <cuda_runtime.h>

// Problem constants
#define FE_    1024
#define FE4_   256            // FE in float4
#define T_     2048
#define B_     4
#define NCH_   32             // chunks over T for the x-sum
#define TPC_   (T_ / NCH_)    // 64 timesteps per chunk
#define EPS_   1e-5f

// Scratch (device globals — allocation is forbidden). float4 for alignment.
__device__ float4 g_ccraw4[2 * FE4_];           // raw Wc@c per branch
__device__ float4 g_cc4[2 * FE4_];              // LayerNormed cond vectors
__device__ float4 g_part4[B_ * NCH_ * FE4_];    // partial sums of x over T
__device__ float4 g_sum4[B_ * FE4_];            // Σ_t x  (pre-modulation)
__device__ float4 g_m24[B_ * FE4_];             // (sv + T·v_bl) ⊙ cc_o
__device__ float4 g_z4[B_ * FE4_];              // final per-batch rows

// ---------------------------------------------------------------------------
// K1 (fused): blocks [0,128): partial x-sum over T.
//             blocks [128,192): cond GEMV  ccraw = Wc @ c_flat  (v & o).
// ---------------------------------------------------------------------------
__global__ void k1_fused(const float4* __restrict__ x4,
                         const float*  __restrict__ c,
                         const float4* __restrict__ vWc4,
                         const float4* __restrict__ oWc4)
{
    const int bid = blockIdx.x;
    const int tid = threadIdx.x;          // 0..255

    if (bid < B_ * NCH_) {
        // ---- x partial sum: one float4 lane per thread, TPC_ timesteps ----
        const int b  = bid / NCH_;
        const int ch = bid % NCH_;
        const float4* p = x4 + (size_t)b * (T_ * FE4_)
                             + (size_t)ch * (TPC_ * FE4_) + tid;
        float4 a = make_float4(0.f, 0.f, 0.f, 0.f);
        #pragma unroll 16
        for (int t = 0; t < TPC_; t++) {
            float4 u = p[(size_t)t * FE4_];
            a.x += u.x; a.y += u.y; a.z += u.z; a.w += u.w;
        }
        g_part4[(size_t)bid * FE4_ + tid] = a;
    } else {
        // ---- cond GEMV: 64 blocks, 32 rows each; warp per row group ----
        const int idx    = bid - B_ * NCH_;   // 0..63
        const int branch = idx >> 5;          // 0=v, 1=o
        const int rblk   = idx & 31;          // 32 row-tiles of 32 rows
        const float4* Wc4 = (branch == 0) ? vWc4 : oWc4;

        __shared__ float4 s_c4[64];           // c_flat: 256 floats
        if (tid < 64) s_c4[tid] = reinterpret_cast<const float4*>(c)[tid];
        __syncthreads();

        const int lane = tid & 31;
        const int warp = tid >> 5;            // 0..7
        float* outp = reinterpret_cast<float*>(g_ccraw4) + branch * FE_;

        #pragma unroll
        for (int rr = 0; rr < 4; rr++) {
            const int row = rblk * 32 + warp * 4 + rr;
            const float4* wr = Wc4 + (size_t)row * 64;   // 256 floats = 64 f4
            float4 w0 = wr[lane], w1 = wr[lane + 32];
            float4 c0 = s_c4[lane], c1 = s_c4[lane + 32];
            float acc = w0.x*c0.x + w0.y*c0.y + w0.z*c0.z + w0.w*c0.w
                      + w1.x*c1.x + w1.y*c1.y + w1.z*c1.z + w1.w*c1.w;
            #pragma unroll
            for (int off = 16; off; off >>= 1)
                acc += __shfl_down_sync(0xffffffffu, acc, off);
            if (lane == 0) outp[row] = acc;
        }
    }
}

// ---------------------------------------------------------------------------
// K2 (tiny): blocks 0,1: LayerNorm of ccraw -> g_cc (two-pass, deterministic).
//            blocks 2..5: reduce g_part -> g_sum for batch (bid-2).
// ---------------------------------------------------------------------------
__global__ void k2_small(const float* __restrict__ vg, const float* __restrict__ vb,
                         const float* __restrict__ og, const float* __restrict__ ob)
{
    const int bid = blockIdx.x;
    const int tid = threadIdx.x;          // 0..255

    if (bid < 2) {
        const float* raw = reinterpret_cast<const float*>(g_ccraw4) + bid * FE_;
        const float* gg  = (bid == 0) ? vg : og;
        const float* bb  = (bid == 0) ? vb : ob;
        float* outp = reinterpret_cast<float*>(g_cc4) + bid * FE_;

        __shared__ float s_red[256];
        float v0 = raw[tid], v1 = raw[tid + 256], v2 = raw[tid + 512], v3 = raw[tid + 768];

        s_red[tid] = v0 + v1 + v2 + v3;
        __syncthreads();
        for (int off = 128; off; off >>= 1) {
            if (tid < off) s_red[tid] += s_red[tid + off];
            __syncthreads();
        }
        const float mu = s_red[0] * (1.0f / FE_);
        __syncthreads();

        float d0 = v0 - mu, d1 = v1 - mu, d2 = v2 - mu, d3 = v3 - mu;
        s_red[tid] = d0*d0 + d1*d1 + d2*d2 + d3*d3;
        __syncthreads();
        for (int off = 128; off; off >>= 1) {
            if (tid < off) s_red[tid] += s_red[tid + off];
            __syncthreads();
        }
        const float rstd = rsqrtf(s_red[0] * (1.0f / FE_) + EPS_);

        outp[tid      ] = d0 * rstd * gg[tid      ] + bb[tid      ];
        outp[tid + 256] = d1 * rstd * gg[tid + 256] + bb[tid + 256];
        outp[tid + 512] = d2 * rstd * gg[tid + 512] + bb[tid + 512];
        outp[tid + 768] = d3 * rstd * gg[tid + 768] + bb[tid + 768];
    } else {
        const int b = bid - 2;
        float4 s = make_float4(0.f, 0.f, 0.f, 0.f);
        #pragma unroll 8
        for (int ch = 0; ch < NCH_; ch++) {
            float4 u = g_part4[((size_t)b * NCH_ + ch) * FE4_ + tid];
            s.x += u.x; s.y += u.y; s.z += u.z; s.w += u.w;
        }
        g_sum4[b * FE4_ + tid] = s;
    }
}

// ---------------------------------------------------------------------------
// K3/K4: batched matvec, 8 rows per block (one warp per row), float4 loads.
// stage 0: m = g_sum ⊙ cc_v;  out g_m2[b][row] = (dot + T·bias[row])·cc_o[row]
// stage 1: m = g_m2;          out g_z [b][row] =  dot + bias[row]
// ---------------------------------------------------------------------------
__global__ void mv_kernel(const float4* __restrict__ W4,
                          const float*  __restrict__ bias,
                          int stage)
{
    __shared__ float4 sm4[B_ * FE4_];      // 16 KB: modulated m, all 4 batches

    const int tid  = threadIdx.x;          // 0..255
    const int lane = tid & 31;
    const int warp = tid >> 5;             // 0..7

    if (stage == 0) {
        const float4* ccv4 = g_cc4;        // branch 0 = cc_v
        #pragma unroll
        for (int i = 0; i < 4; i++) {
            int idx = tid + i * 256;       // b = i, j = tid
            float4 s = g_sum4[idx], cv = ccv4[tid];
            sm4[idx] = make_float4(s.x*cv.x, s.y*cv.y, s.z*cv.z, s.w*cv.w);
        }
    } else {
        #pragma unroll
        for (int i = 0; i < 4; i++) {
            int idx = tid + i * 256;
            sm4[idx] = g_m24[idx];
        }
    }
    __syncthreads();

    const int row = blockIdx.x * 8 + warp;
    const float4* wr = W4 + (size_t)row * FE4_;

    float a0 = 0.f, a1 = 0.f, a2 = 0.f, a3 = 0.f;
    #pragma unroll
    for (int k = 0; k < 8; k++) {
        const int j = lane + k * 32;
        float4 w = wr[j];
        float4 m0 = sm4[j], m1 = sm4[j + 256], m2 = sm4[j + 512], m3 = sm4[j + 768];
        a0 += w.x*m0.x + w.y*m0.y + w.z*m0.z + w.w*m0.w;
        a1 += w.x*m1.x + w.y*m1.y + w.z*m1.z + w.w*m1.w;
        a2 += w.x*m2.x + w.y*m2.y + w.z*m2.z + w.w*m2.w;
        a3 += w.x*m3.x + w.y*m3.y + w.z*m3.z + w.w*m3.w;
    }
    #pragma unroll
    for (int off = 16; off; off >>= 1) {
        a0 += __shfl_down_sync(0xffffffffu, a0, off);
        a1 += __shfl_down_sync(0xffffffffu, a1, off);
        a2 += __shfl_down_sync(0xffffffffu, a2, off);
        a3 += __shfl_down_sync(0xffffffffu, a3, off);
    }
    if (lane == 0) {
        float* out = reinterpret_cast<float*>((stage == 0) ? g_m24 : g_z4);
        if (stage == 0) {
            const float cco = reinterpret_cast<const float*>(g_cc4)[FE_ + row];
            const float bs  = (float)T_ * bias[row];
            out[0 * FE_ + row] = (a0 + bs) * cco;
            out[1 * FE_ + row] = (a1 + bs) * cco;
            out[2 * FE_ + row] = (a2 + bs) * cco;
            out[3 * FE_ + row] = (a3 + bs) * cco;
        } else {
            const float bs = bias[row];
            out[0 * FE_ + row] = a0 + bs;
            out[1 * FE_ + row] = a1 + bs;
            out[2 * FE_ + row] = a2 + bs;
            out[3 * FE_ + row] = a3 + bs;
        }
    }
}

// ---------------------------------------------------------------------------
// K5: broadcast z[b] over T. Each block: one batch row, 16 timesteps.
// ---------------------------------------------------------------------------
__global__ void bcast_kernel(float4* __restrict__ out4)
{
    const int bid = blockIdx.x;            // 0..511
    const int tid = threadIdx.x;           // 0..255
    const int b   = bid >> 7;              // /128
    const int tg  = bid & 127;
    const float4 zv = g_z4[b * FE4_ + tid];
    float4* p = out4 + (size_t)b * (T_ * FE4_) + (size_t)tg * (16 * FE4_) + tid;
    #pragma unroll
    for (int t = 0; t < 16; t++)
        p[(size_t)t * FE4_] = zv;
}

// ---------------------------------------------------------------------------
extern "C" void kernel_launch(void* const* d_in, const int* in_sizes, int n_in,
                              void* d_out, int out_size)
{
    const float* x   = (const float*)d_in[0];
    const float* c   = (const float*)d_in[1];
    // q (3-7), k (8-12) branches and C (2) cancel analytically:
    //   y[b,t] = Σ_u v[b,u]  because Σ_q softmax(...) == 1 and the final
    //   einsum 'bftq,bufe->btfe' sums both q and u independently.
    const float* vWl = (const float*)d_in[13];
    const float* vbl = (const float*)d_in[14];
    const float* vWc = (const float*)d_in[15];
    const float* vg  = (const float*)d_in[16];
    const float* vb  = (const float*)d_in[17];
    const float* oWl = (const float*)d_in[18];
    const float* obl = (const float*)d_in[19];
    const float* oWc = (const float*)d_in[20];
    const float* og  = (const float*)d_in[21];
    const float* ob  = (const float*)d_in[22];

    k1_fused<<<B_ * NCH_ + 64, 256>>>((const float4*)x, c,
                                      (const float4*)vWc, (const float4*)oWc);
    k2_small<<<6, 256>>>(vg, vb, og, ob);
    mv_kernel<<<FE_ / 8, 256>>>((const float4*)vWl, vbl, 0);
    mv_kernel<<<FE_ / 8, 256>>>((const float4*)oWl, obl, 1);
    bcast_kernel<<<B_ * T_ / 16, 256>>>((float4*)d_out);
}

// round 3
// speedup vs baseline: 4.9760x; 1.0556x over previous
#include <cuda_runtime.h>

// Problem constants
#define FE_    1024
#define FE4_   256            // FE in float4
#define T_     2048
#define B_     4
#define NCH_   32             // chunks over T for the x-sum
#define TPC_   (T_ / NCH_)    // 64 timesteps per chunk
#define EPS_   1e-5f

// Scratch (device globals — allocation is forbidden). float4 for alignment.
__device__ float4 g_ccraw4[2 * FE4_];           // raw Wc@c per branch
__device__ float4 g_cc4[2 * FE4_];              // LayerNormed cond vectors
__device__ float4 g_part4[B_ * NCH_ * FE4_];    // partial sums of x over T
__device__ float4 g_sum4[B_ * FE4_];            // Σ_t x  (pre-modulation)
__device__ float4 g_m24[B_ * FE4_];             // (sv + T·v_bl) ⊙ cc_o
__device__ float4 g_z4[B_ * FE4_];              // final per-batch rows

// ---------------------------------------------------------------------------
// K1 (fused): blocks [0,128): partial x-sum over T.
//             blocks [128,192): cond GEMV  ccraw = Wc @ c_flat  (v & o).
// ---------------------------------------------------------------------------
__global__ void k1_fused(const float4* __restrict__ x4,
                         const float*  __restrict__ c,
                         const float4* __restrict__ vWc4,
                         const float4* __restrict__ oWc4)
{
    const int bid = blockIdx.x;
    const int tid = threadIdx.x;          // 0..255

    if (bid < B_ * NCH_) {
        // ---- x partial sum: one float4 lane per thread, TPC_ timesteps ----
        const int b  = bid / NCH_;
        const int ch = bid % NCH_;
        const float4* p = x4 + (size_t)b * (T_ * FE4_)
                             + (size_t)ch * (TPC_ * FE4_) + tid;
        float4 a0 = make_float4(0.f, 0.f, 0.f, 0.f);
        float4 a1 = make_float4(0.f, 0.f, 0.f, 0.f);
        #pragma unroll 8
        for (int t = 0; t < TPC_; t += 2) {
            float4 u = p[(size_t)t * FE4_];
            float4 v = p[(size_t)(t + 1) * FE4_];
            a0.x += u.x; a0.y += u.y; a0.z += u.z; a0.w += u.w;
            a1.x += v.x; a1.y += v.y; a1.z += v.z; a1.w += v.w;
        }
        g_part4[(size_t)bid * FE4_ + tid] =
            make_float4(a0.x + a1.x, a0.y + a1.y, a0.z + a1.z, a0.w + a1.w);
    } else {
        // ---- cond GEMV: 64 blocks, 32 rows each; warp per row group ----
        const int idx    = bid - B_ * NCH_;   // 0..63
        const int branch = idx >> 5;          // 0=v, 1=o
        const int rblk   = idx & 31;          // 32 row-tiles of 32 rows
        const float4* Wc4 = (branch == 0) ? vWc4 : oWc4;

        __shared__ float4 s_c4[64];           // c_flat: 256 floats
        if (tid < 64) s_c4[tid] = reinterpret_cast<const float4*>(c)[tid];
        __syncthreads();

        const int lane = tid & 31;
        const int warp = tid >> 5;            // 0..7
        float* outp = reinterpret_cast<float*>(g_ccraw4) + branch * FE_;

        #pragma unroll
        for (int rr = 0; rr < 4; rr++) {
            const int row = rblk * 32 + warp * 4 + rr;
            const float4* wr = Wc4 + (size_t)row * 64;   // 256 floats = 64 f4
            float4 w0 = wr[lane], w1 = wr[lane + 32];
            float4 c0 = s_c4[lane], c1 = s_c4[lane + 32];
            float acc = w0.x*c0.x + w0.y*c0.y + w0.z*c0.z + w0.w*c0.w
                      + w1.x*c1.x + w1.y*c1.y + w1.z*c1.z + w1.w*c1.w;
            #pragma unroll
            for (int off = 16; off; off >>= 1)
                acc += __shfl_down_sync(0xffffffffu, acc, off);
            if (lane == 0) outp[row] = acc;
        }
    }
}

// ---------------------------------------------------------------------------
// K2 (tiny): blocks 0,1: LayerNorm of ccraw -> g_cc (two-pass, deterministic).
//            blocks 2..5: reduce g_part -> g_sum for batch (bid-2).
// ---------------------------------------------------------------------------
__global__ void k2_small(const float* __restrict__ vg, const float* __restrict__ vb,
                         const float* __restrict__ og, const float* __restrict__ ob)
{
    const int bid = blockIdx.x;
    const int tid = threadIdx.x;          // 0..255

    if (bid < 2) {
        const float* raw = reinterpret_cast<const float*>(g_ccraw4) + bid * FE_;
        const float* gg  = (bid == 0) ? vg : og;
        const float* bb  = (bid == 0) ? vb : ob;
        float* outp = reinterpret_cast<float*>(g_cc4) + bid * FE_;

        __shared__ float s_red[256];
        float v0 = raw[tid], v1 = raw[tid + 256], v2 = raw[tid + 512], v3 = raw[tid + 768];

        s_red[tid] = v0 + v1 + v2 + v3;
        __syncthreads();
        for (int off = 128; off; off >>= 1) {
            if (tid < off) s_red[tid] += s_red[tid + off];
            __syncthreads();
        }
        const float mu = s_red[0] * (1.0f / FE_);
        __syncthreads();

        float d0 = v0 - mu, d1 = v1 - mu, d2 = v2 - mu, d3 = v3 - mu;
        s_red[tid] = d0*d0 + d1*d1 + d2*d2 + d3*d3;
        __syncthreads();
        for (int off = 128; off; off >>= 1) {
            if (tid < off) s_red[tid] += s_red[tid + off];
            __syncthreads();
        }
        const float rstd = rsqrtf(s_red[0] * (1.0f / FE_) + EPS_);

        outp[tid      ] = d0 * rstd * gg[tid      ] + bb[tid      ];
        outp[tid + 256] = d1 * rstd * gg[tid + 256] + bb[tid + 256];
        outp[tid + 512] = d2 * rstd * gg[tid + 512] + bb[tid + 512];
        outp[tid + 768] = d3 * rstd * gg[tid + 768] + bb[tid + 768];
    } else {
        const int b = bid - 2;
        float4 s = make_float4(0.f, 0.f, 0.f, 0.f);
        #pragma unroll 8
        for (int ch = 0; ch < NCH_; ch++) {
            float4 u = g_part4[((size_t)b * NCH_ + ch) * FE4_ + tid];
            s.x += u.x; s.y += u.y; s.z += u.z; s.w += u.w;
        }
        g_sum4[b * FE4_ + tid] = s;
    }
}

// ---------------------------------------------------------------------------
// K3/K4: batched matvec, 8 rows per block (one warp per row).
// All 12 LDG.128 per thread (8 W + 4 m) are issued up front (max MLP), then
// m is staged to smem and the FMAs run out of registers + smem.
// stage 0: m = g_sum ⊙ cc_v;  out g_m2[b][row] = (dot + T·bias[row])·cc_o[row]
// stage 1: m = g_m2;          out g_z [b][row] =  dot + bias[row]
// ---------------------------------------------------------------------------
__global__ void mv_kernel(const float4* __restrict__ W4,
                          const float*  __restrict__ bias,
                          int stage)
{
    __shared__ float4 sm4[B_ * FE4_];      // 16 KB: modulated m, all 4 batches

    const int tid  = threadIdx.x;          // 0..255
    const int lane = tid & 31;
    const int warp = tid >> 5;             // 0..7
    const int row  = blockIdx.x * 8 + warp;
    const float4* wr = W4 + (size_t)row * FE4_;

    // -- front-batched loads: 8 W + 4 m (+1 cc) independent LDG.128 --
    float4 w0 = wr[lane      ], w1 = wr[lane +  32];
    float4 w2 = wr[lane +  64], w3 = wr[lane +  96];
    float4 w4 = wr[lane + 128], w5 = wr[lane + 160];
    float4 w6 = wr[lane + 192], w7 = wr[lane + 224];

    float4 t0, t1, t2, t3;
    if (stage == 0) {
        float4 cv = g_cc4[tid];            // branch 0 = cc_v
        float4 s0 = g_sum4[tid], s1 = g_sum4[tid + 256];
        float4 s2 = g_sum4[tid + 512], s3 = g_sum4[tid + 768];
        t0 = make_float4(s0.x*cv.x, s0.y*cv.y, s0.z*cv.z, s0.w*cv.w);
        t1 = make_float4(s1.x*cv.x, s1.y*cv.y, s1.z*cv.z, s1.w*cv.w);
        t2 = make_float4(s2.x*cv.x, s2.y*cv.y, s2.z*cv.z, s2.w*cv.w);
        t3 = make_float4(s3.x*cv.x, s3.y*cv.y, s3.z*cv.z, s3.w*cv.w);
    } else {
        t0 = g_m24[tid];       t1 = g_m24[tid + 256];
        t2 = g_m24[tid + 512]; t3 = g_m24[tid + 768];
    }
    sm4[tid] = t0; sm4[tid + 256] = t1; sm4[tid + 512] = t2; sm4[tid + 768] = t3;
    __syncthreads();

    float a0 = 0.f, a1 = 0.f, a2 = 0.f, a3 = 0.f;
    {
        float4 wreg[8] = {w0, w1, w2, w3, w4, w5, w6, w7};
        #pragma unroll
        for (int k = 0; k < 8; k++) {
            const int j = lane + k * 32;
            float4 w = wreg[k];
            float4 m0 = sm4[j], m1 = sm4[j + 256], m2 = sm4[j + 512], m3 = sm4[j + 768];
            a0 += w.x*m0.x + w.y*m0.y + w.z*m0.z + w.w*m0.w;
            a1 += w.x*m1.x + w.y*m1.y + w.z*m1.z + w.w*m1.w;
            a2 += w.x*m2.x + w.y*m2.y + w.z*m2.z + w.w*m2.w;
            a3 += w.x*m3.x + w.y*m3.y + w.z*m3.z + w.w*m3.w;
        }
    }
    #pragma unroll
    for (int off = 16; off; off >>= 1) {
        a0 += __shfl_down_sync(0xffffffffu, a0, off);
        a1 += __shfl_down_sync(0xffffffffu, a1, off);
        a2 += __shfl_down_sync(0xffffffffu, a2, off);
        a3 += __shfl_down_sync(0xffffffffu, a3, off);
    }
    if (lane == 0) {
        float* out = reinterpret_cast<float*>((stage == 0) ? g_m24 : g_z4);
        if (stage == 0) {
            const float cco = reinterpret_cast<const float*>(g_cc4)[FE_ + row];
            const float bs  = (float)T_ * bias[row];
            out[0 * FE_ + row] = (a0 + bs) * cco;
            out[1 * FE_ + row] = (a1 + bs) * cco;
            out[2 * FE_ + row] = (a2 + bs) * cco;
            out[3 * FE_ + row] = (a3 + bs) * cco;
        } else {
            const float bs = bias[row];
            out[0 * FE_ + row] = a0 + bs;
            out[1 * FE_ + row] = a1 + bs;
            out[2 * FE_ + row] = a2 + bs;
            out[3 * FE_ + row] = a3 + bs;
        }
    }
}

// ---------------------------------------------------------------------------
// K5: broadcast z[b] over T. Each block: one batch row, 16 timesteps.
// ---------------------------------------------------------------------------
__global__ void bcast_kernel(float4* __restrict__ out4)
{
    const int bid = blockIdx.x;            // 0..511
    const int tid = threadIdx.x;           // 0..255
    const int b   = bid >> 7;              // /128
    const int tg  = bid & 127;
    const float4 zv = g_z4[b * FE4_ + tid];
    float4* p = out4 + (size_t)b * (T_ * FE4_) + (size_t)tg * (16 * FE4_) + tid;
    #pragma unroll
    for (int t = 0; t < 16; t++)
        p[(size_t)t * FE4_] = zv;
}

// ---------------------------------------------------------------------------
extern "C" void kernel_launch(void* const* d_in, const int* in_sizes, int n_in,
                              void* d_out, int out_size)
{
    const float* x   = (const float*)d_in[0];
    const float* c   = (const float*)d_in[1];
    // q (3-7), k (8-12) branches and C (2) cancel analytically:
    //   y[b,t] = Σ_u v[b,u]  because Σ_q softmax(...) == 1 and the final
    //   einsum 'bftq,bufe->btfe' sums both q and u independently.
    const float* vWl = (const float*)d_in[13];
    const float* vbl = (const float*)d_in[14];
    const float* vWc = (const float*)d_in[15];
    const float* vg  = (const float*)d_in[16];
    const float* vb  = (const float*)d_in[17];
    const float* oWl = (const float*)d_in[18];
    const float* obl = (const float*)d_in[19];
    const float* oWc = (const float*)d_in[20];
    const float* og  = (const float*)d_in[21];
    const float* ob  = (const float*)d_in[22];

    k1_fused<<<B_ * NCH_ + 64, 256>>>((const float4*)x, c,
                                      (const float4*)vWc, (const float4*)oWc);
    k2_small<<<6, 256>>>(vg, vb, og, ob);
    mv_kernel<<<FE_ / 8, 256>>>((const float4*)vWl, vbl, 0);
    mv_kernel<<<FE_ / 8, 256>>>((const float4*)oWl, obl, 1);
    bcast_kernel<<<B_ * T_ / 16, 256>>>((float4*)d_out);
}